// round 10
// baseline (speedup 1.0000x reference)
#include <cuda_runtime.h>
#include <cuda_bf16.h>
#include <cuda_fp16.h>
#include <math.h>
#include <stdint.h>

#define BN_ 8
#define C_ 256
#define L_ 4096
#define BL_ (BN_*L_)
#define NCH 128
#define CHK 32
#define POS 32

// ---------------- scratch (device globals) -----------------------------------
__device__ __nv_bfloat16 g_ah[BL_*C_], g_al[BL_*C_];  // activation hi/lo
__device__ float   g_u  [BL_*C_];
__device__ float   g_z  [BL_*C_];
__device__ __half2 g_dtu[2][(size_t)BL_*C_];
__device__ float   g_bc [2][BL_*8];
__device__ float   g_cs [2][BN_*NCH*C_*8];
__device__ float   g_h0 [2][BN_*NCH*C_*4];
__device__ __nv_bfloat16 g_wih[512*256], g_wil[512*256];
__device__ __nv_bfloat16 g_woh[256*256], g_wol[256*256];

// ---------------- helpers -----------------------------------------------------
__device__ __forceinline__ float siluf(float x) { return x / (1.f + __expf(-x)); }

__device__ __forceinline__ uint32_t smem_u32(const void* p) {
    uint32_t a;
    asm("{ .reg .u64 t; cvta.to.shared.u64 t, %1; cvt.u32.u64 %0, t; }" : "=r"(a) : "l"(p));
    return a;
}

__device__ __forceinline__ void mma16816(float* c, const uint32_t* a, const uint32_t* b) {
    asm volatile(
        "mma.sync.aligned.m16n8k16.row.col.f32.bf16.bf16.f32 "
        "{%0,%1,%2,%3}, {%4,%5,%6,%7}, {%8,%9}, {%0,%1,%2,%3};"
        : "+f"(c[0]), "+f"(c[1]), "+f"(c[2]), "+f"(c[3])
        : "r"(a[0]), "r"(a[1]), "r"(a[2]), "r"(a[3]), "r"(b[0]), "r"(b[1]));
}

__device__ __forceinline__ void ldsm4(uint32_t* r, uint32_t addr) {
    asm volatile("ldmatrix.sync.aligned.m8n8.x4.shared.b16 {%0,%1,%2,%3}, [%4];"
        : "=r"(r[0]), "=r"(r[1]), "=r"(r[2]), "=r"(r[3]) : "r"(addr));
}

__device__ __forceinline__ void cpa16(uint32_t dst, const void* src) {
    asm volatile("cp.async.ca.shared.global [%0], [%1], 16;" :: "r"(dst), "l"(src));
}

// ---------------- K0: weight pre-split (both matrices, one launch) -------------
__global__ void wprep_kernel(const float* __restrict__ Wi, const float* __restrict__ Wo) {
    int i = blockIdx.x * 256 + threadIdx.x;
    if (i < 512 * 256) {
        float v = Wi[i];
        __nv_bfloat16 h = __float2bfloat16(v);
        g_wih[i] = h;
        g_wil[i] = __float2bfloat16(v - __bfloat162float(h));
    } else {
        int j = i - 512 * 256;
        float v = Wo[j];
        __nv_bfloat16 h = __float2bfloat16(v);
        g_woh[j] = h;
        g_wol[j] = __float2bfloat16(v - __bfloat162float(h));
    }
}

// ---------------- K1: tiled transpose + LayerNorm -> bf16 hi/lo ----------------
__global__ void ln_kernel(const float* __restrict__ x,
                          const float* __restrict__ wgt,
                          const float* __restrict__ bia) {
    __shared__ float s[C_][33];
    __shared__ float smu[32], srs[32];
    int b = blockIdx.x >> 7;
    int l0 = (blockIdx.x & 127) * 32;
    int tid = threadIdx.x, w = tid >> 5, ln = tid & 31;

    for (int c = w; c < C_; c += 8)
        s[c][ln] = x[((size_t)b * C_ + c) * L_ + l0 + ln];
    __syncthreads();

    #pragma unroll
    for (int j = 0; j < 4; j++) {
        int l = w * 4 + j;
        float sm = 0.f, sq = 0.f;
        #pragma unroll
        for (int i = 0; i < 8; i++) {
            float v = s[ln + 32 * i][l];
            sm += v; sq += v * v;
        }
        #pragma unroll
        for (int o = 16; o; o >>= 1) {
            sm += __shfl_down_sync(0xffffffffu, sm, o);
            sq += __shfl_down_sync(0xffffffffu, sq, o);
        }
        if (ln == 0) {
            float mu = sm * (1.f / C_);
            float var = sq * (1.f / C_) - mu * mu;
            smu[l] = mu; srs[l] = rsqrtf(var + 1e-5f);
        }
    }
    __syncthreads();

    int c = tid;
    float wv = wgt[c], bv = bia[c];
    for (int l = 0; l < 32; l++) {
        float v = (s[c][l] - smu[l]) * srs[l] * wv + bv;
        __nv_bfloat16 h = __float2bfloat16(v);
        size_t o = ((size_t)b * L_ + l0 + l) * C_ + c;
        g_ah[o] = h;
        g_al[o] = __float2bfloat16(v - __bfloat162float(h));
    }
}

// ---------------- K2: cp.async split-bf16 HMMA GEMM, 128x256 block, 64x64 warps -
#define SRK 40
#define A_ROWS 128
#define B_ROWS 256
#define ATILE (A_ROWS * SRK)
#define BTILE (B_ROWS * SRK)
#define BUFE (2 * ATILE + 2 * BTILE)     // elems = 30720
#define BUFB (BUFE * 2)                  // bytes = 61440

__device__ __forceinline__ void gemm_fill(
    uint32_t db, int tid, int kc, int m0, int n0,
    const __nv_bfloat16* Ah, const __nv_bfloat16* Al,
    const __nv_bfloat16* Wh, const __nv_bfloat16* Wl) {
    #pragma unroll
    for (int j = 0; j < 12; j++) {
        int q = tid + j * 256;
        int row = q >> 2, part = q & 3;
        const __nv_bfloat16* src;
        uint32_t doff;
        if (row < 128)      { src = Ah + (size_t)(m0 + row) * 256;       doff = row * SRK; }
        else if (row < 256) { src = Al + (size_t)(m0 + row - 128) * 256; doff = ATILE + (row - 128) * SRK; }
        else if (row < 512) { src = Wh + (size_t)(n0 + row - 256) * 256; doff = 2 * ATILE + (row - 256) * SRK; }
        else                { src = Wl + (size_t)(n0 + row - 512) * 256; doff = 2 * ATILE + BTILE + (row - 512) * SRK; }
        cpa16(db + doff * 2 + part * 16, src + kc * 32 + part * 8);
    }
}

__global__ void __launch_bounds__(256, 1) gemm_hmma(
    const __nv_bfloat16* __restrict__ Ah, const __nv_bfloat16* __restrict__ Al,
    const __nv_bfloat16* __restrict__ Wh, const __nv_bfloat16* __restrict__ Wl,
    float* __restrict__ out0, float* __restrict__ out1,
    const float* __restrict__ xres, int mode) {
    extern __shared__ __nv_bfloat16 sm[];
    uint32_t sbase = smem_u32(sm);

    int tid = threadIdx.x, wid = tid >> 5, lid = tid & 31;
    int g = lid >> 2, t = lid & 3;
    int warp_m = wid & 1, warp_n = wid >> 1;
    int n0 = blockIdx.x * 256, m0 = blockIdx.y * 128;

    float acc[4][8][4] = {};

    // ldmatrix per-lane byte offsets (within a buffer)
    uint32_t aoff = ((warp_m * 64 + (lid & 15)) * SRK + (lid >> 4) * 8) * 2;
    int bn = (lid & 7) + ((lid >> 4) << 3);
    uint32_t boff = ((warp_n * 64 + bn) * SRK + ((lid >> 3) & 1) * 8) * 2;

    // prologue
    gemm_fill(sbase, tid, 0, m0, n0, Ah, Al, Wh, Wl);
    asm volatile("cp.async.commit_group;" ::: "memory");
    gemm_fill(sbase + BUFB, tid, 1, m0, n0, Ah, Al, Wh, Wl);
    asm volatile("cp.async.commit_group;" ::: "memory");

    #pragma unroll
    for (int kc = 0; kc < 8; kc++) {
        if (kc < 6) asm volatile("cp.async.wait_group 1;" ::: "memory");
        else        asm volatile("cp.async.wait_group 0;" ::: "memory");
        __syncthreads();

        uint32_t bb = sbase + (kc & 1) * BUFB;
        uint32_t sAh_b = bb, sAl_b = bb + ATILE * 2;
        uint32_t sBh_b = bb + 4 * ATILE, sBl_b = bb + 4 * ATILE + BTILE * 2;

        #pragma unroll
        for (int ks = 0; ks < 2; ks++) {
            uint32_t bh[4][4], bl[4][4];
            #pragma unroll
            for (int p = 0; p < 4; p++) {
                ldsm4(bh[p], sBh_b + boff + p * 16 * SRK * 2 + ks * 32);
                ldsm4(bl[p], sBl_b + boff + p * 16 * SRK * 2 + ks * 32);
            }
            #pragma unroll
            for (int mi = 0; mi < 4; mi++) {
                uint32_t ah[4], al[4];
                ldsm4(ah, sAh_b + aoff + mi * 16 * SRK * 2 + ks * 32);
                ldsm4(al, sAl_b + aoff + mi * 16 * SRK * 2 + ks * 32);
                #pragma unroll
                for (int ni = 0; ni < 8; ni++) {
                    const uint32_t* bph = &bh[ni >> 1][(ni & 1) * 2];
                    const uint32_t* bpl = &bl[ni >> 1][(ni & 1) * 2];
                    mma16816(acc[mi][ni], ah, bph);
                    mma16816(acc[mi][ni], ah, bpl);
                    mma16816(acc[mi][ni], al, bph);
                }
            }
        }
        __syncthreads();
        if (kc < 6) {
            gemm_fill(sbase + (kc & 1) * BUFB, tid, kc + 2, m0, n0, Ah, Al, Wh, Wl);
            asm volatile("cp.async.commit_group;" ::: "memory");
        }
    }

    if (mode == 0) {
        float* dst = (n0 == 0) ? out0 : out1;
        #pragma unroll
        for (int mi = 0; mi < 4; mi++) {
            int r = m0 + warp_m * 64 + mi * 16 + g;
            #pragma unroll
            for (int ni = 0; ni < 8; ni++) {
                int n = warp_n * 64 + ni * 8 + t * 2;
                *(float2*)&dst[(size_t)r * 256 + n] = make_float2(acc[mi][ni][0], acc[mi][ni][1]);
                *(float2*)&dst[(size_t)(r + 8) * 256 + n] = make_float2(acc[mi][ni][2], acc[mi][ni][3]);
            }
        }
    } else {
        int bb2 = m0 >> 12, l0 = m0 & 4095;
        #pragma unroll
        for (int mi = 0; mi < 4; mi++) {
            int l = l0 + warp_m * 64 + mi * 16 + g;
            #pragma unroll
            for (int ni = 0; ni < 8; ni++) {
                int ch = warp_n * 64 + ni * 8 + t * 2;
                size_t o0 = ((size_t)bb2 * C_ + ch) * L_ + l;
                out0[o0]          = acc[mi][ni][0] + xres[o0];
                out0[o0 + L_]     = acc[mi][ni][1] + xres[o0 + L_];
                out0[o0 + 8]      = acc[mi][ni][2] + xres[o0 + 8];
                out0[o0 + L_ + 8] = acc[mi][ni][3] + xres[o0 + L_ + 8];
            }
        }
    }
}

// ---------------- K3: conv + silu + x_proj + dt_proj + scan-phase1 ------------
__global__ void convscan_kernel(
    const float* __restrict__ cw0, const float* __restrict__ cb0,
    const float* __restrict__ xp0, const float* __restrict__ dw0, const float* __restrict__ db0,
    const float* __restrict__ Alog0,
    const float* __restrict__ cw1, const float* __restrict__ cb1,
    const float* __restrict__ xp1, const float* __restrict__ dw1, const float* __restrict__ db1,
    const float* __restrict__ Alog1) {
    extern __shared__ float sh[];
    float* su   = sh;                  // 35 x 256
    float* sxc  = su + 35 * C_;        // 32 x 256
    float* sxp  = sxc + 32 * C_;       // 24 x 256 ([o][k])
    float* sdwT = sxp + 24 * C_;       // 16 x 256 ([r][c])
    float* sdbl = sdwT + 16 * C_;      // 32 x 24

    int chk = blockIdx.x;
    int b = blockIdx.y >> 1, dir = blockIdx.y & 1;
    const float* cw = dir ? cw1 : cw0;
    const float* cb = dir ? cb1 : cb0;
    const float* xp = dir ? xp1 : xp0;
    const float* dw = dir ? dw1 : dw0;
    const float* db = dir ? db1 : db0;
    const float* Alog = dir ? Alog1 : Alog0;
    int tid = threadIdx.x;
    int q0 = chk * POS;

    for (int i = tid; i < 24 * C_; i += 256) sxp[i] = xp[i];
    for (int i = tid; i < 16 * C_; i += 256) {
        int c = i >> 4, r = i & 15;
        sdwT[r * C_ + c] = dw[i];
    }
    for (int i = tid; i < 35 * C_; i += 256) {
        int j = i >> 8, c2 = i & 255;
        int q = q0 - 3 + j;
        float v = 0.f;
        if (q >= 0) {
            int phys = dir ? (L_ - 1 - q) : q;
            v = g_u[(size_t)(b * L_ + phys) * C_ + c2];
        }
        su[j * C_ + c2] = v;
    }
    __syncthreads();

    {   // conv + silu
        int c = tid;
        float w0 = cw[c], w1 = cw[C_ + c], w2 = cw[2 * C_ + c], w3 = cw[3 * C_ + c];
        float cbv = cb[c];
        #pragma unroll
        for (int tp = 0; tp < POS; tp++) {
            float acc = cbv;
            acc = fmaf(w0, su[(tp + 0) * C_ + c], acc);
            acc = fmaf(w1, su[(tp + 1) * C_ + c], acc);
            acc = fmaf(w2, su[(tp + 2) * C_ + c], acc);
            acc = fmaf(w3, su[(tp + 3) * C_ + c], acc);
            sxc[tp * C_ + c] = siluf(acc);
        }
    }
    __syncthreads();

    {   // x_dbl: independent accumulators first, interleaved shfl trees after
        int w = tid >> 5, ln = tid & 31;
        #pragma unroll 1
        for (int ti = 0; ti < 4; ti++) {
            int tp = w * 4 + ti;
            float xv[8];
            #pragma unroll
            for (int j = 0; j < 8; j++) xv[j] = sxc[tp * C_ + ln + 32 * j];
            float accs[24];
            #pragma unroll
            for (int o = 0; o < 24; o++) {
                float a = 0.f;
                #pragma unroll
                for (int j = 0; j < 8; j++)
                    a = fmaf(xv[j], sxp[o * C_ + ln + 32 * j], a);
                accs[o] = a;
            }
            #pragma unroll
            for (int of = 16; of; of >>= 1)
                #pragma unroll
                for (int o = 0; o < 24; o++)
                    accs[o] += __shfl_down_sync(0xffffffffu, accs[o], of);
            if (ln == 0) {
                #pragma unroll
                for (int o = 0; o < 24; o++) sdbl[tp * 24 + o] = accs[o];
            }
        }
    }
    __syncthreads();

    if (tid < POS * 8) {
        int pos = tid >> 3, v = tid & 7;
        g_bc[dir][(size_t)(b * L_ + q0 + pos) * 8 + v] = sdbl[pos * 24 + 16 + v];
    }

    {   // dt_proj + softplus + chunk summary (fp16-consistent)
        int c = tid;
        float dbv = db[c];
        float Av[4];
        #pragma unroll
        for (int n = 0; n < 4; n++) Av[n] = -__expf(Alog[c * 4 + n]);
        float h[4] = {0, 0, 0, 0}, aP[4] = {1, 1, 1, 1};
        #pragma unroll 1
        for (int pos = 0; pos < POS; pos++) {
            float val = dbv;
            #pragma unroll
            for (int r = 0; r < 16; r++)
                val = fmaf(sdbl[pos * 24 + r], sdwT[r * C_ + c], val);
            float dtv = (val > 20.f) ? val : log1pf(__expf(val));
            float uu = sxc[pos * C_ + c];
            __half2 p = __floats2half2_rn(dtv, uu);
            g_dtu[dir][(size_t)(b * L_ + q0 + pos) * C_ + c] = p;
            float2 q = __half22float2(p);
            float du = q.x * q.y;
            #pragma unroll
            for (int n = 0; n < 4; n++) {
                float a = __expf(q.x * Av[n]);
                h[n] = fmaf(a, h[n], du * sdbl[pos * 24 + 16 + n]);
                aP[n] *= a;
            }
        }
        float* cs = g_cs[dir] + ((size_t)(b * NCH + chk) * C_ + c) * 8;
        #pragma unroll
        for (int n = 0; n < 4; n++) { cs[n * 2] = aP[n]; cs[n * 2 + 1] = h[n]; }
    }
}

// ---------------- K4: scan phase 2 ---------------------------------------------
__global__ void scan2_kernel() {
    int tg = blockIdx.x * 256 + threadIdx.x;
    int bd = tg >> 10;
    int cn = tg & 1023;
    int b = bd >> 1, dir = bd & 1;
    const float2* cs = (const float2*)(g_cs[dir] + (size_t)b * NCH * C_ * 8) + cn;
    float* h0 = g_h0[dir] + (size_t)b * NCH * C_ * 4 + cn;
    float B = 0.f;
    #pragma unroll 8
    for (int ch = 0; ch < NCH; ch++) {
        float2 v = cs[(size_t)ch * 1024];
        h0[(size_t)ch * 1024] = B;
        B = fmaf(v.x, B, v.y);
    }
}

// ---------------- K5: fused replay(f+b) + combine + silu(z) + LN ----------------
__global__ void scan3_fused_kernel(
    const float* __restrict__ Alog0, const float* __restrict__ Alog1,
    const float* __restrict__ D0, const float* __restrict__ D1,
    const float* __restrict__ nw, const float* __restrict__ nb) {
    __shared__ float sbcf[CHK * 8], sbcb[CHK * 8];
    __shared__ float ysm[CHK * C_];
    __shared__ float smu[CHK], srs[CHK];

    int ch = blockIdx.x;
    int b  = blockIdx.y;
    int c  = threadIdx.x;
    int chb = NCH - 1 - ch;
    int l0 = ch * CHK;

    {
        const float* gf = g_bc[0] + (size_t)(b * L_ + ch * CHK) * 8;
        const float* gb = g_bc[1] + (size_t)(b * L_ + chb * CHK) * 8;
        if (c < CHK * 8) { sbcf[c] = gf[c]; sbcb[c] = gb[c]; }
    }
    __syncthreads();

    // forward replay
    {
        float Av[4];
        #pragma unroll
        for (int n = 0; n < 4; n++) Av[n] = -__expf(Alog0[c * 4 + n]);
        float Dv = D0[c];
        const float* h0p = g_h0[0] + ((size_t)(b * NCH + ch) * C_ + c) * 4;
        float h[4];
        #pragma unroll
        for (int n = 0; n < 4; n++) h[n] = h0p[n];
        const __half2* dtu = &g_dtu[0][(size_t)(b * L_ + l0) * C_ + c];
        #pragma unroll 4
        for (int t = 0; t < CHK; t++) {
            float2 v = __half22float2(dtu[(size_t)t * C_]);
            float du = v.x * v.y;
            float y = v.y * Dv;
            #pragma unroll
            for (int n = 0; n < 4; n++) {
                float a = __expf(v.x * Av[n]);
                h[n] = fmaf(a, h[n], du * sbcf[t * 8 + n]);
                y = fmaf(h[n], sbcf[t * 8 + 4 + n], y);
            }
            ysm[t * C_ + c] = y;
        }
    }
    // backward replay
    {
        float Av[4];
        #pragma unroll
        for (int n = 0; n < 4; n++) Av[n] = -__expf(Alog1[c * 4 + n]);
        float Dv = D1[c];
        const float* h0p = g_h0[1] + ((size_t)(b * NCH + chb) * C_ + c) * 4;
        float h[4];
        #pragma unroll
        for (int n = 0; n < 4; n++) h[n] = h0p[n];
        const __half2* dtu = &g_dtu[1][(size_t)(b * L_ + chb * CHK) * C_ + c];
        #pragma unroll 4
        for (int tb = 0; tb < CHK; tb++) {
            float2 v = __half22float2(dtu[(size_t)tb * C_]);
            float du = v.x * v.y;
            float y = v.y * Dv;
            #pragma unroll
            for (int n = 0; n < 4; n++) {
                float a = __expf(v.x * Av[n]);
                h[n] = fmaf(a, h[n], du * sbcb[tb * 8 + n]);
                y = fmaf(h[n], sbcb[tb * 8 + 4 + n], y);
            }
            ysm[(CHK - 1 - tb) * C_ + c] += y;
        }
    }
    // z-gate
    {
        const float* zp = &g_z[(size_t)(b * L_ + l0) * C_ + c];
        #pragma unroll 4
        for (int t = 0; t < CHK; t++) {
            float z = zp[(size_t)t * C_];
            ysm[t * C_ + c] = 0.5f * ysm[t * C_ + c] * siluf(z);
        }
    }
    __syncthreads();
    // LN stats
    {
        int w = c >> 5, ln = c & 31;
        #pragma unroll
        for (int j = 0; j < 4; j++) {
            int t = w * 4 + j;
            float sm = 0.f, sq = 0.f;
            #pragma unroll
            for (int i = 0; i < 8; i++) {
                float v = ysm[t * C_ + ln + 32 * i];
                sm += v; sq += v * v;
            }
            #pragma unroll
            for (int o = 16; o; o >>= 1) {
                sm += __shfl_down_sync(0xffffffffu, sm, o);
                sq += __shfl_down_sync(0xffffffffu, sq, o);
            }
            if (ln == 0) {
                float mu = sm * (1.f / C_);
                float var = sq * (1.f / C_) - mu * mu;
                smu[t] = mu; srs[t] = rsqrtf(var + 1e-5f);
            }
        }
    }
    __syncthreads();
    {
        float wv = nw[c], bv = nb[c];
        #pragma unroll 4
        for (int t = 0; t < CHK; t++) {
            float v = (ysm[t * C_ + c] - smu[t]) * srs[t] * wv + bv;
            __nv_bfloat16 hh = __float2bfloat16(v);
            size_t o = (size_t)(b * L_ + l0 + t) * C_ + c;
            g_ah[o] = hh;
            g_al[o] = __float2bfloat16(v - __bfloat162float(hh));
        }
    }
}

// ---------------- launch ---------------------------------------------------------
extern "C" void kernel_launch(void* const* d_in, const int* in_sizes, int n_in,
                              void* d_out, int out_size) {
    const float* x        = (const float*)d_in[0];
    const float* ln_w     = (const float*)d_in[1];
    const float* ln_b     = (const float*)d_in[2];
    const float* in_proj  = (const float*)d_in[3];
    const float* cw_f     = (const float*)d_in[4];
    const float* cb_f     = (const float*)d_in[5];
    const float* xp_f     = (const float*)d_in[6];
    const float* dw_f     = (const float*)d_in[7];
    const float* db_f     = (const float*)d_in[8];
    const float* Alog_f   = (const float*)d_in[9];
    const float* D_f      = (const float*)d_in[10];
    const float* cw_b     = (const float*)d_in[11];
    const float* cb_b     = (const float*)d_in[12];
    const float* xp_b     = (const float*)d_in[13];
    const float* dw_b     = (const float*)d_in[14];
    const float* db_b     = (const float*)d_in[15];
    const float* Alog_b   = (const float*)d_in[16];
    const float* D_b      = (const float*)d_in[17];
    const float* nrm_w    = (const float*)d_in[18];
    const float* nrm_b    = (const float*)d_in[19];
    const float* out_proj = (const float*)d_in[20];
    float* out = (float*)d_out;

    float* gu;  cudaGetSymbolAddress((void**)&gu,  g_u);
    float* gz;  cudaGetSymbolAddress((void**)&gz,  g_z);
    __nv_bfloat16 *gah, *gal, *wih, *wil, *woh, *wol;
    cudaGetSymbolAddress((void**)&gah, g_ah);
    cudaGetSymbolAddress((void**)&gal, g_al);
    cudaGetSymbolAddress((void**)&wih, g_wih);
    cudaGetSymbolAddress((void**)&wil, g_wil);
    cudaGetSymbolAddress((void**)&woh, g_woh);
    cudaGetSymbolAddress((void**)&wol, g_wol);

    const int gemm_smem = 2 * BUFB;   // 122880 B
    cudaFuncSetAttribute(gemm_hmma, cudaFuncAttributeMaxDynamicSharedMemorySize, gemm_smem);
    const int conv_smem = (35 * C_ + 32 * C_ + 24 * C_ + 16 * C_ + 32 * 24) * 4;
    cudaFuncSetAttribute(convscan_kernel, cudaFuncAttributeMaxDynamicSharedMemorySize, conv_smem);

    // 0. weight pre-split (one launch, both matrices)
    wprep_kernel<<<768, 256>>>(in_proj, out_proj);
    // 1. LN
    ln_kernel<<<BN_ * 128, 256>>>(x, ln_w, ln_b);
    // 2. in_proj GEMM (32768 x 512): grid (2, 256), block tile 128x256
    gemm_hmma<<<dim3(2, BL_ / 128), 256, gemm_smem>>>(gah, gal, wih, wil, gu, gz, nullptr, 0);
    // 3. conv + silu + x_proj + dt_proj + scan-phase1
    convscan_kernel<<<dim3(NCH, BN_ * 2), 256, conv_smem>>>(
        cw_f, cb_f, xp_f, dw_f, db_f, Alog_f,
        cw_b, cb_b, xp_b, dw_b, db_b, Alog_b);
    // 4. scan phase 2
    scan2_kernel<<<64, 256>>>();
    // 5. fused replay + combine + silu(z) + LN
    scan3_fused_kernel<<<dim3(NCH, BN_), 256>>>(Alog_f, Alog_b, D_f, D_b, nrm_w, nrm_b);
    // 6. out_proj GEMM + residual + transposed write: grid (1, 256)
    gemm_hmma<<<dim3(1, BL_ / 128), 256, gemm_smem>>>(gah, gal, woh, wol, out, nullptr, x, 1);
}

// round 11
// speedup vs baseline: 1.2537x; 1.2537x over previous
#include <cuda_runtime.h>
#include <cuda_bf16.h>
#include <cuda_fp16.h>
#include <math.h>
#include <stdint.h>

#define BN_ 8
#define C_ 256
#define L_ 4096
#define BL_ (BN_*L_)
#define NCH 128
#define CHK 32
#define POS 32

// ---------------- scratch (device globals) -----------------------------------
__device__ __nv_bfloat16 g_ah[BL_*C_], g_al[BL_*C_];  // activation hi/lo
__device__ float   g_u  [BL_*C_];
__device__ float   g_z  [BL_*C_];
__device__ __half2 g_dtu[2][(size_t)BL_*C_];
__device__ float   g_bc [2][BL_*8];
__device__ float   g_cs [2][BN_*NCH*C_*8];
__device__ float   g_h0 [2][BN_*NCH*C_*4];
__device__ __nv_bfloat16 g_wih[512*256], g_wil[512*256];
__device__ __nv_bfloat16 g_woh[256*256], g_wol[256*256];

// ---------------- helpers -----------------------------------------------------
__device__ __forceinline__ float siluf(float x) { return x / (1.f + __expf(-x)); }

__device__ __forceinline__ uint32_t smem_u32(const void* p) {
    uint32_t a;
    asm("{ .reg .u64 t; cvta.to.shared.u64 t, %1; cvt.u32.u64 %0, t; }" : "=r"(a) : "l"(p));
    return a;
}

__device__ __forceinline__ void mma16816(float* c, const uint32_t* a, const uint32_t* b) {
    asm volatile(
        "mma.sync.aligned.m16n8k16.row.col.f32.bf16.bf16.f32 "
        "{%0,%1,%2,%3}, {%4,%5,%6,%7}, {%8,%9}, {%0,%1,%2,%3};"
        : "+f"(c[0]), "+f"(c[1]), "+f"(c[2]), "+f"(c[3])
        : "r"(a[0]), "r"(a[1]), "r"(a[2]), "r"(a[3]), "r"(b[0]), "r"(b[1]));
}

__device__ __forceinline__ void ldsm4(uint32_t* r, uint32_t addr) {
    asm volatile("ldmatrix.sync.aligned.m8n8.x4.shared.b16 {%0,%1,%2,%3}, [%4];"
        : "=r"(r[0]), "=r"(r[1]), "=r"(r[2]), "=r"(r[3]) : "r"(addr));
}

__device__ __forceinline__ void cpa16(uint32_t dst, const void* src) {
    asm volatile("cp.async.ca.shared.global [%0], [%1], 16;" :: "r"(dst), "l"(src));
}

// ---------------- K0: weight pre-split ------------------------------------------
__global__ void wprep_kernel(const float* __restrict__ Wi, const float* __restrict__ Wo) {
    int i = blockIdx.x * 256 + threadIdx.x;
    if (i < 512 * 256) {
        float v = Wi[i];
        __nv_bfloat16 h = __float2bfloat16(v);
        g_wih[i] = h;
        g_wil[i] = __float2bfloat16(v - __bfloat162float(h));
    } else {
        int j = i - 512 * 256;
        float v = Wo[j];
        __nv_bfloat16 h = __float2bfloat16(v);
        g_woh[j] = h;
        g_wol[j] = __float2bfloat16(v - __bfloat162float(h));
    }
}

// ---------------- K1: tiled transpose + LayerNorm -> bf16 hi/lo ----------------
__global__ void ln_kernel(const float* __restrict__ x,
                          const float* __restrict__ wgt,
                          const float* __restrict__ bia) {
    __shared__ float s[C_][33];
    __shared__ float smu[32], srs[32];
    int b = blockIdx.x >> 7;
    int l0 = (blockIdx.x & 127) * 32;
    int tid = threadIdx.x, w = tid >> 5, ln = tid & 31;

    for (int c = w; c < C_; c += 8)
        s[c][ln] = x[((size_t)b * C_ + c) * L_ + l0 + ln];
    __syncthreads();

    #pragma unroll
    for (int j = 0; j < 4; j++) {
        int l = w * 4 + j;
        float sm = 0.f, sq = 0.f;
        #pragma unroll
        for (int i = 0; i < 8; i++) {
            float v = s[ln + 32 * i][l];
            sm += v; sq += v * v;
        }
        #pragma unroll
        for (int o = 16; o; o >>= 1) {
            sm += __shfl_down_sync(0xffffffffu, sm, o);
            sq += __shfl_down_sync(0xffffffffu, sq, o);
        }
        if (ln == 0) {
            float mu = sm * (1.f / C_);
            float var = sq * (1.f / C_) - mu * mu;
            smu[l] = mu; srs[l] = rsqrtf(var + 1e-5f);
        }
    }
    __syncthreads();

    int c = tid;
    float wv = wgt[c], bv = bia[c];
    for (int l = 0; l < 32; l++) {
        float v = (s[c][l] - smu[l]) * srs[l] * wv + bv;
        __nv_bfloat16 h = __float2bfloat16(v);
        size_t o = ((size_t)b * L_ + l0 + l) * C_ + c;
        g_ah[o] = h;
        g_al[o] = __float2bfloat16(v - __bfloat162float(h));
    }
}

// ---------------- K2: double-buffered cp.async split-bf16 HMMA GEMM ------------
// (round-9 known-good version: 128x128 tile, 64x32 warp tiles)
#define SR 72
#define TILE_ELEM (128 * SR)
#define BUF_BYTES (4 * TILE_ELEM * 2)      // 73728
__global__ void __launch_bounds__(256, 1) gemm_hmma(
    const __nv_bfloat16* __restrict__ Ah, const __nv_bfloat16* __restrict__ Al,
    const __nv_bfloat16* __restrict__ Wh, const __nv_bfloat16* __restrict__ Wl,
    float* __restrict__ out0, float* __restrict__ out1,
    const float* __restrict__ xres, int mode) {
    extern __shared__ __nv_bfloat16 sm[];
    uint32_t sbase = smem_u32(sm);

    int tid = threadIdx.x, wid = tid >> 5, lid = tid & 31;
    int g = lid >> 2, t = lid & 3;
    int warp_m = wid & 1, warp_n = wid >> 1;
    int n0 = blockIdx.x * 128, m0 = blockIdx.y * 128;

    float acc[4][4][4] = {};

    int frow = tid >> 1;
    int fkh = (tid & 1) * 32;
    const __nv_bfloat16* srcs[4];
    srcs[0] = Ah + (size_t)(m0 + frow) * 256 + fkh;
    srcs[1] = Al + (size_t)(m0 + frow) * 256 + fkh;
    srcs[2] = Wh + (size_t)(n0 + frow) * 256 + fkh;
    srcs[3] = Wl + (size_t)(n0 + frow) * 256 + fkh;
    uint32_t fill_dst = sbase + (frow * SR + fkh) * 2;

    uint32_t aoff = ((warp_m * 64 + (lid & 15)) * SR + (lid >> 4) * 8) * 2;
    int bn = (lid & 7) + ((lid >> 4) << 3);
    uint32_t boff = ((warp_n * 32 + bn) * SR + ((lid >> 3) & 1) * 8) * 2;

    #pragma unroll
    for (int p = 0; p < 2; p++) {
        uint32_t db = fill_dst + p * BUF_BYTES;
        #pragma unroll
        for (int tno = 0; tno < 4; tno++)
            #pragma unroll
            for (int j = 0; j < 4; j++)
                cpa16(db + tno * (TILE_ELEM * 2) + j * 16, srcs[tno] + p * 64 + j * 8);
        asm volatile("cp.async.commit_group;" ::: "memory");
    }

    #pragma unroll
    for (int kc = 0; kc < 4; kc++) {
        if (kc < 3) asm volatile("cp.async.wait_group 1;" ::: "memory");
        else        asm volatile("cp.async.wait_group 0;" ::: "memory");
        __syncthreads();

        uint32_t bb = sbase + (kc & 1) * BUF_BYTES;
        uint32_t sAh_b = bb, sAl_b = bb + TILE_ELEM * 2;
        uint32_t sBh_b = bb + TILE_ELEM * 4, sBl_b = bb + TILE_ELEM * 6;

        #pragma unroll
        for (int ks = 0; ks < 4; ks++) {
            uint32_t bh[2][4], bl[2][4];
            ldsm4(bh[0], sBh_b + boff + ks * 32);
            ldsm4(bh[1], sBh_b + boff + 16 * SR * 2 + ks * 32);
            ldsm4(bl[0], sBl_b + boff + ks * 32);
            ldsm4(bl[1], sBl_b + boff + 16 * SR * 2 + ks * 32);
            #pragma unroll
            for (int mi = 0; mi < 4; mi++) {
                uint32_t ah[4], al[4];
                ldsm4(ah, sAh_b + aoff + mi * 16 * SR * 2 + ks * 32);
                ldsm4(al, sAl_b + aoff + mi * 16 * SR * 2 + ks * 32);
                #pragma unroll
                for (int ni = 0; ni < 4; ni++) {
                    const uint32_t* bph = &bh[ni >> 1][(ni & 1) * 2];
                    const uint32_t* bpl = &bl[ni >> 1][(ni & 1) * 2];
                    mma16816(acc[mi][ni], ah, bph);
                    mma16816(acc[mi][ni], ah, bpl);
                    mma16816(acc[mi][ni], al, bph);
                }
            }
        }
        __syncthreads();
        if (kc < 2) {
            uint32_t db = fill_dst + (kc & 1) * BUF_BYTES;
            #pragma unroll
            for (int tno = 0; tno < 4; tno++)
                #pragma unroll
                for (int j = 0; j < 4; j++)
                    cpa16(db + tno * (TILE_ELEM * 2) + j * 16, srcs[tno] + (kc + 2) * 64 + j * 8);
            asm volatile("cp.async.commit_group;" ::: "memory");
        }
    }

    if (mode == 0) {
        float* dst = (n0 < 256) ? out0 : out1;
        int nb = n0 & 255;
        #pragma unroll
        for (int mi = 0; mi < 4; mi++) {
            int r = m0 + warp_m * 64 + mi * 16 + g;
            #pragma unroll
            for (int ni = 0; ni < 4; ni++) {
                int n = nb + warp_n * 32 + ni * 8 + t * 2;
                *(float2*)&dst[(size_t)r * 256 + n] = make_float2(acc[mi][ni][0], acc[mi][ni][1]);
                *(float2*)&dst[(size_t)(r + 8) * 256 + n] = make_float2(acc[mi][ni][2], acc[mi][ni][3]);
            }
        }
    } else {
        int bb2 = m0 >> 12, l0 = m0 & 4095;
        #pragma unroll
        for (int mi = 0; mi < 4; mi++) {
            int l = l0 + warp_m * 64 + mi * 16 + g;
            #pragma unroll
            for (int ni = 0; ni < 4; ni++) {
                int ch = n0 + warp_n * 32 + ni * 8 + t * 2;
                size_t o0 = ((size_t)bb2 * C_ + ch) * L_ + l;
                out0[o0]          = acc[mi][ni][0] + xres[o0];
                out0[o0 + L_]     = acc[mi][ni][1] + xres[o0 + L_];
                out0[o0 + 8]      = acc[mi][ni][2] + xres[o0 + 8];
                out0[o0 + L_ + 8] = acc[mi][ni][3] + xres[o0 + L_ + 8];
            }
        }
    }
}

// ---------------- K3: conv + silu + x_proj + dt_proj + scan-phase1 -------------
// 75 KB smem, regs capped at 128 -> 2 CTAs/SM
__global__ void __launch_bounds__(256, 2) convscan_kernel(
    const float* __restrict__ cw0, const float* __restrict__ cb0,
    const float* __restrict__ xp0, const float* __restrict__ dw0, const float* __restrict__ db0,
    const float* __restrict__ Alog0,
    const float* __restrict__ cw1, const float* __restrict__ cb1,
    const float* __restrict__ xp1, const float* __restrict__ dw1, const float* __restrict__ db1,
    const float* __restrict__ Alog1) {
    extern __shared__ float sh[];
    float* sxc  = sh;                  // 32 x 256
    float* sxp  = sxc + 32 * C_;       // 24 x 256 ([o][k])
    float* sdwT = sxp + 24 * C_;       // 16 x 256 ([r][c])
    float* sdbl = sdwT + 16 * C_;      // 32 x 24

    int chk = blockIdx.x;
    int b = blockIdx.y >> 1, dir = blockIdx.y & 1;
    const float* cw = dir ? cw1 : cw0;
    const float* cb = dir ? cb1 : cb0;
    const float* xp = dir ? xp1 : xp0;
    const float* dw = dir ? dw1 : dw0;
    const float* db = dir ? db1 : db0;
    const float* Alog = dir ? Alog1 : Alog0;
    int tid = threadIdx.x;
    int q0 = chk * POS;

    for (int i = tid; i < 24 * C_; i += 256) sxp[i] = xp[i];
    for (int i = tid; i < 16 * C_; i += 256) {
        int c = i >> 4, r = i & 15;
        sdwT[r * C_ + c] = dw[i];
    }

    {   // conv + silu: rolling 4-register window over g_u, no smem staging
        int c = tid;
        float w0 = cw[c], w1 = cw[C_ + c], w2 = cw[2 * C_ + c], w3 = cw[3 * C_ + c];
        float cbv = cb[c];
        float u0 = 0.f, u1 = 0.f, u2 = 0.f;
        #pragma unroll
        for (int j = 0; j < 3; j++) {
            int q = q0 - 3 + j;
            float v = 0.f;
            if (q >= 0) {
                int phys = dir ? (L_ - 1 - q) : q;
                v = g_u[(size_t)(b * L_ + phys) * C_ + c];
            }
            if (j == 0) u0 = v; else if (j == 1) u1 = v; else u2 = v;
        }
        #pragma unroll 4
        for (int tp = 0; tp < POS; tp++) {
            int q = q0 + tp;
            int phys = dir ? (L_ - 1 - q) : q;
            float u3 = g_u[(size_t)(b * L_ + phys) * C_ + c];
            float acc = cbv;
            acc = fmaf(w0, u0, acc);
            acc = fmaf(w1, u1, acc);
            acc = fmaf(w2, u2, acc);
            acc = fmaf(w3, u3, acc);
            sxc[tp * C_ + c] = siluf(acc);
            u0 = u1; u1 = u2; u2 = u3;
        }
    }
    __syncthreads();

    {   // x_dbl: 3 batches of 8 outputs (bounded regs, good ILP)
        int w = tid >> 5, ln = tid & 31;
        #pragma unroll 1
        for (int ti = 0; ti < 4; ti++) {
            int tp = w * 4 + ti;
            float xv[8];
            #pragma unroll
            for (int j = 0; j < 8; j++) xv[j] = sxc[tp * C_ + ln + 32 * j];
            #pragma unroll 1
            for (int b3 = 0; b3 < 3; b3++) {
                float accs[8];
                #pragma unroll
                for (int o = 0; o < 8; o++) {
                    int o2 = b3 * 8 + o;
                    float a = 0.f;
                    #pragma unroll
                    for (int j = 0; j < 8; j++)
                        a = fmaf(xv[j], sxp[o2 * C_ + ln + 32 * j], a);
                    accs[o] = a;
                }
                #pragma unroll
                for (int of = 16; of; of >>= 1)
                    #pragma unroll
                    for (int o = 0; o < 8; o++)
                        accs[o] += __shfl_down_sync(0xffffffffu, accs[o], of);
                if (ln == 0) {
                    #pragma unroll
                    for (int o = 0; o < 8; o++) sdbl[tp * 24 + b3 * 8 + o] = accs[o];
                }
            }
        }
    }
    __syncthreads();

    if (tid < POS * 8) {
        int pos = tid >> 3, v = tid & 7;
        g_bc[dir][(size_t)(b * L_ + q0 + pos) * 8 + v] = sdbl[pos * 24 + 16 + v];
    }

    {   // dt_proj + softplus + chunk summary (fp16-consistent)
        int c = tid;
        float dbv = db[c];
        float Av[4];
        #pragma unroll
        for (int n = 0; n < 4; n++) Av[n] = -__expf(Alog[c * 4 + n]);
        float h[4] = {0, 0, 0, 0}, aP[4] = {1, 1, 1, 1};
        #pragma unroll 1
        for (int pos = 0; pos < POS; pos++) {
            float val = dbv;
            #pragma unroll
            for (int r = 0; r < 16; r++)
                val = fmaf(sdbl[pos * 24 + r], sdwT[r * C_ + c], val);
            float dtv = (val > 20.f) ? val : log1pf(__expf(val));
            float uu = sxc[pos * C_ + c];
            __half2 p = __floats2half2_rn(dtv, uu);
            g_dtu[dir][(size_t)(b * L_ + q0 + pos) * C_ + c] = p;
            float2 q = __half22float2(p);
            float du = q.x * q.y;
            #pragma unroll
            for (int n = 0; n < 4; n++) {
                float a = __expf(q.x * Av[n]);
                h[n] = fmaf(a, h[n], du * sdbl[pos * 24 + 16 + n]);
                aP[n] *= a;
            }
        }
        float* cs = g_cs[dir] + ((size_t)(b * NCH + chk) * C_ + c) * 8;
        #pragma unroll
        for (int n = 0; n < 4; n++) { cs[n * 2] = aP[n]; cs[n * 2 + 1] = h[n]; }
    }
}

// ---------------- K4: scan phase 2 ---------------------------------------------
__global__ void scan2_kernel() {
    int tg = blockIdx.x * 256 + threadIdx.x;
    int bd = tg >> 10;
    int cn = tg & 1023;
    int b = bd >> 1, dir = bd & 1;
    const float2* cs = (const float2*)(g_cs[dir] + (size_t)b * NCH * C_ * 8) + cn;
    float* h0 = g_h0[dir] + (size_t)b * NCH * C_ * 4 + cn;
    float B = 0.f;
    #pragma unroll 8
    for (int ch = 0; ch < NCH; ch++) {
        float2 v = cs[(size_t)ch * 1024];
        h0[(size_t)ch * 1024] = B;
        B = fmaf(v.x, B, v.y);
    }
}

// ---------------- K5: fused replay(f+b) + combine + silu(z) + LN ----------------
__global__ void scan3_fused_kernel(
    const float* __restrict__ Alog0, const float* __restrict__ Alog1,
    const float* __restrict__ D0, const float* __restrict__ D1,
    const float* __restrict__ nw, const float* __restrict__ nb) {
    __shared__ float sbcf[CHK * 8], sbcb[CHK * 8];
    __shared__ float ysm[CHK * C_];
    __shared__ float smu[CHK], srs[CHK];

    int ch = blockIdx.x;
    int b  = blockIdx.y;
    int c  = threadIdx.x;
    int chb = NCH - 1 - ch;
    int l0 = ch * CHK;

    {
        const float* gf = g_bc[0] + (size_t)(b * L_ + ch * CHK) * 8;
        const float* gb = g_bc[1] + (size_t)(b * L_ + chb * CHK) * 8;
        if (c < CHK * 8) { sbcf[c] = gf[c]; sbcb[c] = gb[c]; }
    }
    __syncthreads();

    // forward replay
    {
        float Av[4];
        #pragma unroll
        for (int n = 0; n < 4; n++) Av[n] = -__expf(Alog0[c * 4 + n]);
        float Dv = D0[c];
        const float* h0p = g_h0[0] + ((size_t)(b * NCH + ch) * C_ + c) * 4;
        float h[4];
        #pragma unroll
        for (int n = 0; n < 4; n++) h[n] = h0p[n];
        const __half2* dtu = &g_dtu[0][(size_t)(b * L_ + l0) * C_ + c];
        #pragma unroll 4
        for (int t = 0; t < CHK; t++) {
            float2 v = __half22float2(dtu[(size_t)t * C_]);
            float du = v.x * v.y;
            float y = v.y * Dv;
            #pragma unroll
            for (int n = 0; n < 4; n++) {
                float a = __expf(v.x * Av[n]);
                h[n] = fmaf(a, h[n], du * sbcf[t * 8 + n]);
                y = fmaf(h[n], sbcf[t * 8 + 4 + n], y);
            }
            ysm[t * C_ + c] = y;
        }
    }
    // backward replay
    {
        float Av[4];
        #pragma unroll
        for (int n = 0; n < 4; n++) Av[n] = -__expf(Alog1[c * 4 + n]);
        float Dv = D1[c];
        const float* h0p = g_h0[1] + ((size_t)(b * NCH + chb) * C_ + c) * 4;
        float h[4];
        #pragma unroll
        for (int n = 0; n < 4; n++) h[n] = h0p[n];
        const __half2* dtu = &g_dtu[1][(size_t)(b * L_ + chb * CHK) * C_ + c];
        #pragma unroll 4
        for (int tb = 0; tb < CHK; tb++) {
            float2 v = __half22float2(dtu[(size_t)tb * C_]);
            float du = v.x * v.y;
            float y = v.y * Dv;
            #pragma unroll
            for (int n = 0; n < 4; n++) {
                float a = __expf(v.x * Av[n]);
                h[n] = fmaf(a, h[n], du * sbcb[tb * 8 + n]);
                y = fmaf(h[n], sbcb[tb * 8 + 4 + n], y);
            }
            ysm[(CHK - 1 - tb) * C_ + c] += y;
        }
    }
    // z-gate
    {
        const float* zp = &g_z[(size_t)(b * L_ + l0) * C_ + c];
        #pragma unroll 4
        for (int t = 0; t < CHK; t++) {
            float z = zp[(size_t)t * C_];
            ysm[t * C_ + c] = 0.5f * ysm[t * C_ + c] * siluf(z);
        }
    }
    __syncthreads();
    // LN stats
    {
        int w = c >> 5, ln = c & 31;
        #pragma unroll
        for (int j = 0; j < 4; j++) {
            int t = w * 4 + j;
            float sm = 0.f, sq = 0.f;
            #pragma unroll
            for (int i = 0; i < 8; i++) {
                float v = ysm[t * C_ + ln + 32 * i];
                sm += v; sq += v * v;
            }
            #pragma unroll
            for (int o = 16; o; o >>= 1) {
                sm += __shfl_down_sync(0xffffffffu, sm, o);
                sq += __shfl_down_sync(0xffffffffu, sq, o);
            }
            if (ln == 0) {
                float mu = sm * (1.f / C_);
                float var = sq * (1.f / C_) - mu * mu;
                smu[t] = mu; srs[t] = rsqrtf(var + 1e-5f);
            }
        }
    }
    __syncthreads();
    {
        float wv = nw[c], bv = nb[c];
        #pragma unroll 4
        for (int t = 0; t < CHK; t++) {
            float v = (ysm[t * C_ + c] - smu[t]) * srs[t] * wv + bv;
            __nv_bfloat16 hh = __float2bfloat16(v);
            size_t o = (size_t)(b * L_ + l0 + t) * C_ + c;
            g_ah[o] = hh;
            g_al[o] = __float2bfloat16(v - __bfloat162float(hh));
        }
    }
}

// ---------------- launch ---------------------------------------------------------
extern "C" void kernel_launch(void* const* d_in, const int* in_sizes, int n_in,
                              void* d_out, int out_size) {
    const float* x        = (const float*)d_in[0];
    const float* ln_w     = (const float*)d_in[1];
    const float* ln_b     = (const float*)d_in[2];
    const float* in_proj  = (const float*)d_in[3];
    const float* cw_f     = (const float*)d_in[4];
    const float* cb_f     = (const float*)d_in[5];
    const float* xp_f     = (const float*)d_in[6];
    const float* dw_f     = (const float*)d_in[7];
    const float* db_f     = (const float*)d_in[8];
    const float* Alog_f   = (const float*)d_in[9];
    const float* D_f      = (const float*)d_in[10];
    const float* cw_b     = (const float*)d_in[11];
    const float* cb_b     = (const float*)d_in[12];
    const float* xp_b     = (const float*)d_in[13];
    const float* dw_b     = (const float*)d_in[14];
    const float* db_b     = (const float*)d_in[15];
    const float* Alog_b   = (const float*)d_in[16];
    const float* D_b      = (const float*)d_in[17];
    const float* nrm_w    = (const float*)d_in[18];
    const float* nrm_b    = (const float*)d_in[19];
    const float* out_proj = (const float*)d_in[20];
    float* out = (float*)d_out;

    float* gu;  cudaGetSymbolAddress((void**)&gu,  g_u);
    float* gz;  cudaGetSymbolAddress((void**)&gz,  g_z);
    __nv_bfloat16 *gah, *gal, *wih, *wil, *woh, *wol;
    cudaGetSymbolAddress((void**)&gah, g_ah);
    cudaGetSymbolAddress((void**)&gal, g_al);
    cudaGetSymbolAddress((void**)&wih, g_wih);
    cudaGetSymbolAddress((void**)&wil, g_wil);
    cudaGetSymbolAddress((void**)&woh, g_woh);
    cudaGetSymbolAddress((void**)&wol, g_wol);

    const int gemm_smem = 2 * BUF_BYTES;   // 147456 B
    cudaFuncSetAttribute(gemm_hmma, cudaFuncAttributeMaxDynamicSharedMemorySize, gemm_smem);
    const int conv_smem = (32 * C_ + 24 * C_ + 16 * C_ + 32 * 24) * 4;   // ~75 KB
    cudaFuncSetAttribute(convscan_kernel, cudaFuncAttributeMaxDynamicSharedMemorySize, conv_smem);

    wprep_kernel<<<768, 256>>>(in_proj, out_proj);
    ln_kernel<<<BN_ * 128, 256>>>(x, ln_w, ln_b);
    gemm_hmma<<<dim3(4, BL_ / 128), 256, gemm_smem>>>(gah, gal, wih, wil, gu, gz, nullptr, 0);
    convscan_kernel<<<dim3(NCH, BN_ * 2), 256, conv_smem>>>(
        cw_f, cb_f, xp_f, dw_f, db_f, Alog_f,
        cw_b, cb_b, xp_b, dw_b, db_b, Alog_b);
    scan2_kernel<<<64, 256>>>();
    scan3_fused_kernel<<<dim3(NCH, BN_), 256>>>(Alog_f, Alog_b, D_f, D_b, nrm_w, nrm_b);
    gemm_hmma<<<dim3(2, BL_ / 128), 256, gemm_smem>>>(gah, gal, woh, wol, out, nullptr, x, 1);
}